// round 8
// baseline (speedup 1.0000x reference)
#include <cuda_runtime.h>
#include <cuda_bf16.h>
#include <cstdint>

// Problem constants
#define NB     32          // batch
#define HW     4096        // 64*64
#define FD     256         // feat dim
#define HD     128         // dense hidden
#define HS     128         // sparse hidden
#define NT     8           // num tokens
#define DENSE_OUT_ELEMS (NB * FD * HW)   // 33554432

// Scratch (device global: no allocation allowed)
__device__ float g_scale_buf[NB * HW];          // (1 + sim)

// ---------------------------------------------------------------------------
// helpers
// ---------------------------------------------------------------------------
__device__ __forceinline__ float f2tf32(float x) {
    uint32_t u;
    asm("cvt.rna.tf32.f32 %0, %1;" : "=r"(u) : "f"(x));
    return __uint_as_float(u);
}

__device__ __forceinline__ void mma_tf32(float acc[4],
                                         uint32_t a0, uint32_t a1, uint32_t a2, uint32_t a3,
                                         uint32_t b0, uint32_t b1) {
    asm volatile(
        "mma.sync.aligned.m16n8k8.row.col.f32.tf32.tf32.f32 "
        "{%0,%1,%2,%3},{%4,%5,%6,%7},{%8,%9},{%0,%1,%2,%3};\n"
        : "+f"(acc[0]), "+f"(acc[1]), "+f"(acc[2]), "+f"(acc[3])
        : "r"(a0), "r"(a1), "r"(a2), "r"(a3), "r"(b0), "r"(b1));
}

__device__ __forceinline__ uint32_t fu(float x) { return __float_as_uint(x); }

// ---------------------------------------------------------------------------
// Kernel 1: dense path (fused sim + featk + GEMM1(relu) + GEMM2), writes sim scale
// Block: 256 threads (8 warps: wm = wid&3 handles 16 M-rows, wn = wid>>2 splits N)
// Tile: 64 rows (hw) x 256 channels.
// Grid: x = batch (32), y = hw-tile (64)  -> consecutive bids share weight slabs
// in L2 during wave 1 while spreading feat reads across batches.
// smem layout (floats):
//   Xs  [0      .. 16896)  : featk tile, stride 260  (phase 2: W2 half, stride 132)
//   Ws  [16896  .. 25600)  : W1 k-slab [128 x 68]    (phase 2: OUT staging [128 x 68])
//   Hs  [25600  .. 34048)  : hidden tile [64 x 132]
//   Ps  [34048  .. 34304)  : prototype (256)
//   Ss  [34304  .. 34368)  : per-row scale (64)
// ---------------------------------------------------------------------------
#define K2_SMEM_FLOATS 34368
#define K2_SMEM_BYTES  (K2_SMEM_FLOATS * 4)

__global__ __launch_bounds__(256)
void k_dense(const float* __restrict__ feat, const float* __restrict__ proto,
             const float* __restrict__ w1, const float* __restrict__ b1v,
             const float* __restrict__ w2, const float* __restrict__ b2v,
             float* __restrict__ outd) {
    const int b   = blockIdx.x;
    const int hw0 = blockIdx.y * 64;

    extern __shared__ float sm[];
    float* Xs = sm;             // stride 260 (phase 0/1), W2 half stride 132 (phase 2)
    float* Ws = sm + 16896;     // stride 68
    float* Hs = sm + 25600;     // stride 132
    float* Ps = sm + 34048;
    float* Ss = sm + 34304;

    const int tid  = threadIdx.x;
    const int lane = tid & 31;
    const int wid  = tid >> 5;
    const int g    = lane >> 2;
    const int tg   = lane & 3;
    const int wm   = wid & 3;   // M quadrant (16 rows)
    const int wn   = wid >> 2;  // N half

    // --- phase 0: load tile, compute sim, scale, round to tf32 ---
    Ps[tid] = proto[tid];  // blockDim == 256 == FD
    const float* fb = feat + ((size_t)(b * HW + hw0)) * FD;
    for (int i = tid; i < 64 * 64; i += 256) {
        int r = i >> 6, c4 = (i & 63) << 2;
        float4 v = *reinterpret_cast<const float4*>(fb + r * FD + c4);
        *reinterpret_cast<float4*>(Xs + r * 260 + c4) = v;
    }
    __syncthreads();

    for (int rr = 0; rr < 8; rr++) {
        int r = wid * 8 + rr;
        float a = 0.f;
#pragma unroll
        for (int j = 0; j < 8; j++) a += Xs[r * 260 + lane + 32 * j] * Ps[lane + 32 * j];
#pragma unroll
        for (int o = 16; o; o >>= 1) a += __shfl_xor_sync(0xffffffffu, a, o);
        if (lane == 0) {
            float s = 1.f + a;
            Ss[r] = s;
            g_scale_buf[b * HW + hw0 + r] = s;
        }
    }
    __syncthreads();

    for (int i = tid; i < 64 * 256; i += 256) {
        int r = i >> 8, c = i & 255;
        Xs[r * 260 + c] = f2tf32(Xs[r * 260 + c] * Ss[r]);
    }

    // --- phase 1: GEMM1  H[64x128] = featk[64x256] @ W1^T ---
    float acc[8][4];
#pragma unroll
    for (int j = 0; j < 8; j++)
#pragma unroll
        for (int q = 0; q < 4; q++) acc[j][q] = 0.f;

    for (int ks = 0; ks < 4; ks++) {
        for (int i = tid; i < 2048; i += 256) {  // W1 slab [128 o x 64 k]
            int o = i >> 4, c4 = (i & 15) << 2;
            float4 v = *reinterpret_cast<const float4*>(w1 + o * FD + ks * 64 + c4);
            Ws[o * 68 + c4 + 0] = f2tf32(v.x);
            Ws[o * 68 + c4 + 1] = f2tf32(v.y);
            Ws[o * 68 + c4 + 2] = f2tf32(v.z);
            Ws[o * 68 + c4 + 3] = f2tf32(v.w);
        }
        __syncthreads();
#pragma unroll
        for (int kk = 0; kk < 8; kk++) {
            int kc = ks * 64 + kk * 8;
            uint32_t a0 = fu(Xs[(wm * 16 + g) * 260 + kc + tg]);
            uint32_t a1 = fu(Xs[(wm * 16 + g + 8) * 260 + kc + tg]);
            uint32_t a2 = fu(Xs[(wm * 16 + g) * 260 + kc + tg + 4]);
            uint32_t a3 = fu(Xs[(wm * 16 + g + 8) * 260 + kc + tg + 4]);
#pragma unroll
            for (int j = 0; j < 8; j++) {
                int o = (wn * 8 + j) * 8 + g;
                uint32_t bb0 = fu(Ws[o * 68 + kk * 8 + tg]);
                uint32_t bb1 = fu(Ws[o * 68 + kk * 8 + tg + 4]);
                mma_tf32(acc[j], a0, a1, a2, a3, bb0, bb1);
            }
        }
        __syncthreads();
    }

    // bias + relu -> Hs (tf32)
#pragma unroll
    for (int j = 0; j < 8; j++) {
        int n0 = (wn * 8 + j) * 8 + 2 * tg;
        float bb0 = __ldg(b1v + n0), bb1 = __ldg(b1v + n0 + 1);
        int r0 = wm * 16 + g;
        Hs[r0 * 132 + n0]           = f2tf32(fmaxf(acc[j][0] + bb0, 0.f));
        Hs[r0 * 132 + n0 + 1]       = f2tf32(fmaxf(acc[j][1] + bb1, 0.f));
        Hs[(r0 + 8) * 132 + n0]     = f2tf32(fmaxf(acc[j][2] + bb0, 0.f));
        Hs[(r0 + 8) * 132 + n0 + 1] = f2tf32(fmaxf(acc[j][3] + bb1, 0.f));
    }

    // --- phase 2: GEMM2  OUT[64x256] = relu(H)[64x128] @ W2^T, two N-halves ---
    for (int h2 = 0; h2 < 2; h2++) {
        __syncthreads();  // Hs ready / previous half done with Xs & Ws
        for (int i = tid; i < 4096; i += 256) {  // W2 half [128 n x 128 k]
            int n = i >> 5, k4 = (i & 31) << 2;
            float4 v = *reinterpret_cast<const float4*>(w2 + (size_t)(h2 * 128 + n) * 128 + k4);
            Xs[n * 132 + k4 + 0] = f2tf32(v.x);
            Xs[n * 132 + k4 + 1] = f2tf32(v.y);
            Xs[n * 132 + k4 + 2] = f2tf32(v.z);
            Xs[n * 132 + k4 + 3] = f2tf32(v.w);
        }
        __syncthreads();

        float acc2[8][4];
#pragma unroll
        for (int j = 0; j < 8; j++)
#pragma unroll
            for (int q = 0; q < 4; q++) acc2[j][q] = 0.f;

#pragma unroll
        for (int kk = 0; kk < 16; kk++) {
            int kc = kk * 8;
            uint32_t a0 = fu(Hs[(wm * 16 + g) * 132 + kc + tg]);
            uint32_t a1 = fu(Hs[(wm * 16 + g + 8) * 132 + kc + tg]);
            uint32_t a2 = fu(Hs[(wm * 16 + g) * 132 + kc + tg + 4]);
            uint32_t a3 = fu(Hs[(wm * 16 + g + 8) * 132 + kc + tg + 4]);
#pragma unroll
            for (int j = 0; j < 8; j++) {
                int n = (wn * 8 + j) * 8 + g;
                uint32_t bb0 = fu(Xs[n * 132 + kc + tg]);
                uint32_t bb1 = fu(Xs[n * 132 + kc + tg + 4]);
                mma_tf32(acc2[j], a0, a1, a2, a3, bb0, bb1);
            }
        }

        // stage [n_local][m] into Ws (stride 68) for coalesced channel-major store
#pragma unroll
        for (int j = 0; j < 8; j++) {
            int n0 = (wn * 8 + j) * 8 + 2 * tg;
            float bb0 = __ldg(b2v + h2 * 128 + n0), bb1 = __ldg(b2v + h2 * 128 + n0 + 1);
            int m0 = wm * 16 + g;
            Ws[n0 * 68 + m0]           = acc2[j][0] + bb0;
            Ws[(n0 + 1) * 68 + m0]     = acc2[j][1] + bb1;
            Ws[n0 * 68 + m0 + 8]       = acc2[j][2] + bb0;
            Ws[(n0 + 1) * 68 + m0 + 8] = acc2[j][3] + bb1;
        }
        __syncthreads();

        for (int i = tid; i < 2048; i += 256) {
            int n = i >> 4, m4 = (i & 15) << 2;
            float4 v = *reinterpret_cast<float4*>(Ws + n * 68 + m4);
            *reinterpret_cast<float4*>(outd + ((size_t)(b * FD + h2 * 128 + n)) * HW + hw0 + m4) = v;
        }
    }
}

// ---------------------------------------------------------------------------
// Kernel 2: FUSED sparse path:
//   hs[o,c] = relu( sum_i featk[b,i,c]*w1[o,i] + b1[o] )           (tf32 MMA)
//   out[b,t,c] = sum_o hs[o,c]*w2[t,o] + b2[t] + emb_pos[t,c]      (block reduce)
// Block per (c-tile of 64, batch); each block holds ALL 128 o-rows across its
// 8 warps, so conv2 completes in-block with no global hs scratch.
// smem: As = w_sparse1 slab [128 x 68] -> (epilogue) hs staging [128 x 68]
//       Bs = featk slab [64 x 68]      -> (epilogue) w_sparse2 [8 x 128]
// ---------------------------------------------------------------------------
#define K3_SMEM_FLOATS (8704 + 4352)
#define K3_SMEM_BYTES  (K3_SMEM_FLOATS * 4)

__global__ __launch_bounds__(256)
void k_sparse(const float* __restrict__ feat, const float* __restrict__ w1,
              const float* __restrict__ b1v, const float* __restrict__ w2,
              const float* __restrict__ b2, const float* __restrict__ embp,
              float* __restrict__ outs) {
    const int b  = blockIdx.y;
    const int c0 = blockIdx.x * 64;

    extern __shared__ float sm[];
    float* As = sm;           // [128][68]
    float* Bs = sm + 8704;    // [64][68]

    const int tid  = threadIdx.x;
    const int lane = tid & 31;
    const int wm   = tid >> 5;       // 0..7 -> o rows [16*wm, 16*wm+16)
    const int g    = lane >> 2;
    const int tg   = lane & 3;

    float acc[8][4];
#pragma unroll
    for (int j = 0; j < 8; j++)
#pragma unroll
        for (int q = 0; q < 4; q++) acc[j][q] = 0.f;

    for (int ks = 0; ks < 64; ks++) {
        const int i0 = ks * 64;
        for (int i = tid; i < 2048; i += 256) {   // w1 slab
            int o = i >> 4, c4 = (i & 15) << 2;
            float4 v = *reinterpret_cast<const float4*>(w1 + (size_t)o * HW + i0 + c4);
            As[o * 68 + c4 + 0] = f2tf32(v.x);
            As[o * 68 + c4 + 1] = f2tf32(v.y);
            As[o * 68 + c4 + 2] = f2tf32(v.z);
            As[o * 68 + c4 + 3] = f2tf32(v.w);
        }
        for (int i = tid; i < 1024; i += 256) {   // featk slab (apply 1+sim)
            int r = i >> 4, c4 = (i & 15) << 2;
            float s = __ldg(g_scale_buf + b * HW + i0 + r);
            float4 v = *reinterpret_cast<const float4*>(
                feat + ((size_t)(b * HW + i0 + r)) * FD + c0 + c4);
            Bs[r * 68 + c4 + 0] = f2tf32(v.x * s);
            Bs[r * 68 + c4 + 1] = f2tf32(v.y * s);
            Bs[r * 68 + c4 + 2] = f2tf32(v.z * s);
            Bs[r * 68 + c4 + 3] = f2tf32(v.w * s);
        }
        __syncthreads();
#pragma unroll
        for (int kk = 0; kk < 8; kk++) {
            uint32_t a0 = fu(As[(wm * 16 + g) * 68 + kk * 8 + tg]);
            uint32_t a1 = fu(As[(wm * 16 + g + 8) * 68 + kk * 8 + tg]);
            uint32_t a2 = fu(As[(wm * 16 + g) * 68 + kk * 8 + tg + 4]);
            uint32_t a3 = fu(As[(wm * 16 + g + 8) * 68 + kk * 8 + tg + 4]);
#pragma unroll
            for (int j = 0; j < 8; j++) {
                uint32_t bb0 = fu(Bs[(kk * 8 + tg) * 68 + j * 8 + g]);
                uint32_t bb1 = fu(Bs[(kk * 8 + tg + 4) * 68 + j * 8 + g]);
                mma_tf32(acc[j], a0, a1, a2, a3, bb0, bb1);
            }
        }
        __syncthreads();   // also protects the epilogue's As/Bs overwrite below
    }

    // --- epilogue A: bias + relu, stage hs into As [o][c_local] (stride 68) ---
    {
        const int o0 = wm * 16 + g;
        float bb0 = __ldg(b1v + o0), bb1 = __ldg(b1v + o0 + 8);
#pragma unroll
        for (int j = 0; j < 8; j++) {
            int cl = j * 8 + 2 * tg;
            As[o0 * 68 + cl]           = fmaxf(acc[j][0] + bb0, 0.f);
            As[o0 * 68 + cl + 1]       = fmaxf(acc[j][1] + bb0, 0.f);
            As[(o0 + 8) * 68 + cl]     = fmaxf(acc[j][2] + bb1, 0.f);
            As[(o0 + 8) * 68 + cl + 1] = fmaxf(acc[j][3] + bb1, 0.f);
        }
    }
    // load w_sparse2 [8 x 128] into Bs
    for (int i = tid; i < NT * HS; i += 256) Bs[i] = w2[i];
    __syncthreads();

    // --- epilogue B: conv2 + bias + emb_pos. 512 outputs, 2 per thread ---
#pragma unroll
    for (int q = 0; q < 2; q++) {
        int idx = tid + 256 * q;            // 0..511
        int t  = idx >> 6;                  // 0..7
        int cl = idx & 63;
        float a = 0.f;
#pragma unroll 8
        for (int o = 0; o < HS; o++) a += As[o * 68 + cl] * Bs[t * HS + o];
        int c = c0 + cl;
        outs[b * (NT * FD) + t * FD + c] = a + __ldg(b2 + t) + __ldg(embp + t * FD + c);
    }
}

// ---------------------------------------------------------------------------
// launcher
// ---------------------------------------------------------------------------
extern "C" void kernel_launch(void* const* d_in, const int* in_sizes, int n_in,
                              void* d_out, int out_size) {
    (void)out_size;
    const float* feat  = (const float*)d_in[0];
    const float* proto = (const float*)d_in[1];
    // d_in[2] = cls_ids (all ones). "num_classes" is a Python scalar in the
    // reference inputs dict: the harness may or may not materialize it as a
    // device input. Detect the layout instead of hard-coding it:
    //   14 inputs -> num_classes present at [3], weights start at [4]
    //   13 inputs -> num_classes absent,      weights start at [3]
    int s = (n_in >= 14) ? 0 : -1;
    // Sanity: w_dense1 must have HD*FD = 32768 elements. If the scalar slot
    // exists but n_in parsing was wrong, fall back by probing sizes.
    if (in_sizes[4 + s] != HD * FD) {
        if (in_sizes[3] == HD * FD)      s = -1;
        else if (in_sizes[4] == HD * FD) s = 0;
    }
    const float* w_d1 = (const float*)d_in[4 + s];
    const float* b_d1 = (const float*)d_in[5 + s];
    const float* w_d2 = (const float*)d_in[6 + s];
    const float* b_d2 = (const float*)d_in[7 + s];
    const float* w_s1 = (const float*)d_in[8 + s];
    const float* b_s1 = (const float*)d_in[9 + s];
    const float* w_s2 = (const float*)d_in[10 + s];
    const float* b_s2 = (const float*)d_in[11 + s];
    // [12+s] = emb_neg (unused: one_hot == 1 for NUM_CLS=1, cls_ids=1)
    const float* embp = (const float*)d_in[13 + s];
    float* out = (float*)d_out;

    cudaFuncSetAttribute(k_dense,  cudaFuncAttributeMaxDynamicSharedMemorySize, K2_SMEM_BYTES);
    cudaFuncSetAttribute(k_sparse, cudaFuncAttributeMaxDynamicSharedMemorySize, K3_SMEM_BYTES);

    // dense path + write (1+sim) scratch  (grid: x=batch, y=hw-tile)
    k_dense<<<dim3(32, 64), 256, K2_SMEM_BYTES>>>(feat, proto, w_d1, b_d1, w_d2, b_d2, out);
    // fused sparse path (reads scratch written by k_dense; same stream -> ordered)
    k_sparse<<<dim3(4, 32), 256, K3_SMEM_BYTES>>>(feat, w_s1, b_s1, w_s2, b_s2, embp,
                                                  out + DENSE_OUT_ELEMS);
}

// round 10
// speedup vs baseline: 1.6278x; 1.6278x over previous
#include <cuda_runtime.h>
#include <cuda_bf16.h>
#include <cstdint>

// Problem constants
#define NB     32          // batch
#define HW     4096        // 64*64
#define FD     256         // feat dim
#define HD     128         // dense hidden
#define HS     128         // sparse hidden
#define NT     8           // num tokens
#define NSPLIT 8           // k_sparse split-K factor
#define DENSE_OUT_ELEMS (NB * FD * HW)   // 33554432

// Scratch (device globals: no allocation allowed)
__device__ float g_scale_buf[NB * HW];                    // (1 + sim)
__device__ float g_part[NSPLIT * NB * HS * FD];           // split-K partials (33.5 MB)

// ---------------------------------------------------------------------------
// helpers
// ---------------------------------------------------------------------------
__device__ __forceinline__ float f2tf32(float x) {
    uint32_t u;
    asm("cvt.rna.tf32.f32 %0, %1;" : "=r"(u) : "f"(x));
    return __uint_as_float(u);
}

__device__ __forceinline__ void mma_tf32(float acc[4],
                                         uint32_t a0, uint32_t a1, uint32_t a2, uint32_t a3,
                                         uint32_t b0, uint32_t b1) {
    asm volatile(
        "mma.sync.aligned.m16n8k8.row.col.f32.tf32.tf32.f32 "
        "{%0,%1,%2,%3},{%4,%5,%6,%7},{%8,%9},{%0,%1,%2,%3};\n"
        : "+f"(acc[0]), "+f"(acc[1]), "+f"(acc[2]), "+f"(acc[3])
        : "r"(a0), "r"(a1), "r"(a2), "r"(a3), "r"(b0), "r"(b1));
}

__device__ __forceinline__ uint32_t fu(float x) { return __float_as_uint(x); }

__device__ __forceinline__ uint32_t smu32(const void* p) {
    return (uint32_t)__cvta_generic_to_shared(p);
}
#define CPA16(dst_u32, src_ptr) \
    asm volatile("cp.async.cg.shared.global [%0], [%1], 16;" :: "r"(dst_u32), "l"(src_ptr))
#define CPA_COMMIT()  asm volatile("cp.async.commit_group;" ::: "memory")
#define CPA_WAIT0()   asm volatile("cp.async.wait_group 0;" ::: "memory")
#define CPA_WAIT1()   asm volatile("cp.async.wait_group 1;" ::: "memory")

// ---------------------------------------------------------------------------
// Kernel 1: dense path (fused sim + featk + GEMM1(relu) + GEMM2), writes scale.
// 256 threads / 8 warps.  Weight operands loaded RAW via cp.async (HW tf32
// truncation); featk/H cvt.rna.  W1 slabs double-buffered; slab0 + feat tile
// prefetched before phase-0 compute.
// smem (floats): Xs[0,16896) s260 | Ws0[16896,25600) s68 | Ws1[25600,34304) s68
//                Hs[34304,42752) s132 | Ps[42752,43008) | Ss[43008,43072)
// ---------------------------------------------------------------------------
#define K2_SMEM_FLOATS 43072
#define K2_SMEM_BYTES  (K2_SMEM_FLOATS * 4)

__global__ __launch_bounds__(256)
void k_dense(const float* __restrict__ feat, const float* __restrict__ proto,
             const float* __restrict__ w1, const float* __restrict__ b1v,
             const float* __restrict__ w2, const float* __restrict__ b2v,
             float* __restrict__ outd) {
    const int b   = blockIdx.x;
    const int hw0 = blockIdx.y * 64;

    extern __shared__ float sm[];
    float* Xs  = sm;            // featk (s260); phase 2: W2 half (s132)
    float* Ws0 = sm + 16896;    // W1 slab buf A (s68); phase 2: out staging
    float* Ws1 = sm + 25600;    // W1 slab buf B (s68)
    float* Hs  = sm + 34304;    // hidden (s132)
    float* Ps  = sm + 42752;
    float* Ss  = sm + 43008;
    float* Wbuf[2] = {Ws0, Ws1};

    const int tid  = threadIdx.x;
    const int lane = tid & 31;
    const int wid  = tid >> 5;
    const int g    = lane >> 2;
    const int tg   = lane & 3;
    const int wm   = wid & 3;
    const int wn   = wid >> 2;

    // --- prologue: async-prefetch feat tile and W1 slab 0 ---
    const float* fb = feat + ((size_t)(b * HW + hw0)) * FD;
    for (int i = tid; i < 4096; i += 256) {          // 64 rows x 64 float4
        int r = i >> 6, c4 = (i & 63) << 2;
        CPA16(smu32(Xs + r * 260 + c4), fb + r * FD + c4);
    }
    CPA_COMMIT();                                    // group: feat
    for (int i = tid; i < 2048; i += 256) {          // W1 slab0 [128 x 64]
        int o = i >> 4, c4 = (i & 15) << 2;
        CPA16(smu32(Ws0 + o * 68 + c4), w1 + o * FD + c4);
    }
    CPA_COMMIT();                                    // group: slab0
    Ps[tid] = proto[tid];
    CPA_WAIT1();                                     // feat landed; slab0 may fly
    __syncthreads();

    // --- phase 0: sim + scale + cvt ---
    for (int rr = 0; rr < 8; rr++) {
        int r = wid * 8 + rr;
        float a = 0.f;
#pragma unroll
        for (int j = 0; j < 8; j++) a += Xs[r * 260 + lane + 32 * j] * Ps[lane + 32 * j];
#pragma unroll
        for (int o = 16; o; o >>= 1) a += __shfl_xor_sync(0xffffffffu, a, o);
        if (lane == 0) {
            float s = 1.f + a;
            Ss[r] = s;
            g_scale_buf[b * HW + hw0 + r] = s;
        }
    }
    __syncthreads();
    for (int i = tid; i < 64 * 256; i += 256) {
        int r = i >> 8, c = i & 255;
        Xs[r * 260 + c] = f2tf32(Xs[r * 260 + c] * Ss[r]);
    }
    // (first phase-1 barrier covers this pass)

    // --- phase 1: GEMM1  H[64x128] = featk @ W1^T, double-buffered slabs ---
    float acc[8][4];
#pragma unroll
    for (int j = 0; j < 8; j++)
#pragma unroll
        for (int q = 0; q < 4; q++) acc[j][q] = 0.f;

    for (int ks = 0; ks < 4; ks++) {
        CPA_WAIT0();             // slab ks landed
        __syncthreads();         // visible to all; prev MMA done (WAR safe)
        if (ks < 3) {            // prefetch next slab into other buffer
            float* nb = Wbuf[(ks + 1) & 1];
            for (int i = tid; i < 2048; i += 256) {
                int o = i >> 4, c4 = (i & 15) << 2;
                CPA16(smu32(nb + o * 68 + c4), w1 + o * FD + (ks + 1) * 64 + c4);
            }
            CPA_COMMIT();
        }
        const float* Wc = Wbuf[ks & 1];
#pragma unroll
        for (int kk = 0; kk < 8; kk++) {
            int kc = ks * 64 + kk * 8;
            uint32_t a0 = fu(Xs[(wm * 16 + g) * 260 + kc + tg]);
            uint32_t a1 = fu(Xs[(wm * 16 + g + 8) * 260 + kc + tg]);
            uint32_t a2 = fu(Xs[(wm * 16 + g) * 260 + kc + tg + 4]);
            uint32_t a3 = fu(Xs[(wm * 16 + g + 8) * 260 + kc + tg + 4]);
#pragma unroll
            for (int j = 0; j < 8; j++) {
                int o = (wn * 8 + j) * 8 + g;
                uint32_t bb0 = fu(Wc[o * 68 + kk * 8 + tg]);
                uint32_t bb1 = fu(Wc[o * 68 + kk * 8 + tg + 4]);
                mma_tf32(acc[j], a0, a1, a2, a3, bb0, bb1);
            }
        }
    }

    // bias + relu -> Hs (tf32); each thread writes its own cells
#pragma unroll
    for (int j = 0; j < 8; j++) {
        int n0 = (wn * 8 + j) * 8 + 2 * tg;
        float bb0 = __ldg(b1v + n0), bb1 = __ldg(b1v + n0 + 1);
        int r0 = wm * 16 + g;
        Hs[r0 * 132 + n0]           = f2tf32(fmaxf(acc[j][0] + bb0, 0.f));
        Hs[r0 * 132 + n0 + 1]       = f2tf32(fmaxf(acc[j][1] + bb1, 0.f));
        Hs[(r0 + 8) * 132 + n0]     = f2tf32(fmaxf(acc[j][2] + bb0, 0.f));
        Hs[(r0 + 8) * 132 + n0 + 1] = f2tf32(fmaxf(acc[j][3] + bb1, 0.f));
    }

    // --- phase 2: OUT[64x256] = relu(H) @ W2^T, two N-halves ---
    for (int h2 = 0; h2 < 2; h2++) {
        __syncthreads();  // Hs ready / Xs & Ws0 free
        for (int i = tid; i < 4096; i += 256) {  // W2 half [128 x 128] raw
            int n = i >> 5, k4 = (i & 31) << 2;
            CPA16(smu32(Xs + n * 132 + k4), w2 + (size_t)(h2 * 128 + n) * 128 + k4);
        }
        CPA_COMMIT();
        CPA_WAIT0();
        __syncthreads();

        float acc2[8][4];
#pragma unroll
        for (int j = 0; j < 8; j++)
#pragma unroll
            for (int q = 0; q < 4; q++) acc2[j][q] = 0.f;

#pragma unroll
        for (int kk = 0; kk < 16; kk++) {
            int kc = kk * 8;
            uint32_t a0 = fu(Hs[(wm * 16 + g) * 132 + kc + tg]);
            uint32_t a1 = fu(Hs[(wm * 16 + g + 8) * 132 + kc + tg]);
            uint32_t a2 = fu(Hs[(wm * 16 + g) * 132 + kc + tg + 4]);
            uint32_t a3 = fu(Hs[(wm * 16 + g + 8) * 132 + kc + tg + 4]);
#pragma unroll
            for (int j = 0; j < 8; j++) {
                int n = (wn * 8 + j) * 8 + g;
                uint32_t bb0 = fu(Xs[n * 132 + kc + tg]);
                uint32_t bb1 = fu(Xs[n * 132 + kc + tg + 4]);
                mma_tf32(acc2[j], a0, a1, a2, a3, bb0, bb1);
            }
        }

        // stage [n][m] into Ws0 for coalesced channel-major store
#pragma unroll
        for (int j = 0; j < 8; j++) {
            int n0 = (wn * 8 + j) * 8 + 2 * tg;
            float bb0 = __ldg(b2v + h2 * 128 + n0), bb1 = __ldg(b2v + h2 * 128 + n0 + 1);
            int m0 = wm * 16 + g;
            Ws0[n0 * 68 + m0]           = acc2[j][0] + bb0;
            Ws0[(n0 + 1) * 68 + m0]     = acc2[j][1] + bb1;
            Ws0[n0 * 68 + m0 + 8]       = acc2[j][2] + bb0;
            Ws0[(n0 + 1) * 68 + m0 + 8] = acc2[j][3] + bb1;
        }
        __syncthreads();

        for (int i = tid; i < 2048; i += 256) {
            int n = i >> 4, m4 = (i & 15) << 2;
            float4 v = *reinterpret_cast<float4*>(Ws0 + n * 68 + m4);
            *reinterpret_cast<float4*>(outd + ((size_t)(b * FD + h2 * 128 + n)) * HW + hw0 + m4) = v;
        }
    }
}

// ---------------------------------------------------------------------------
// Kernel 2: sparse conv1, SPLIT-K x8.  Each block: (c-tile 64, batch, split)
// contracts 512 hw rows, writes fp32 partials (no bias/relu) to g_part.
// w1 slabs via cp.async (raw f32); feat slab synchronous (overlaps the async).
// ---------------------------------------------------------------------------
#define K3_SMEM_FLOATS (8704 + 4352)
#define K3_SMEM_BYTES  (K3_SMEM_FLOATS * 4)

__global__ __launch_bounds__(256)
void k_sparse(const float* __restrict__ feat, const float* __restrict__ w1) {
    const int b   = blockIdx.y;
    const int c0  = blockIdx.x * 64;
    const int sp  = blockIdx.z;

    extern __shared__ float sm[];
    float* As = sm;           // w1 slab [128][68]
    float* Bs = sm + 8704;    // featk slab [64][68]

    const int tid  = threadIdx.x;
    const int lane = tid & 31;
    const int wm   = tid >> 5;
    const int g    = lane >> 2;
    const int tg   = lane & 3;

    float acc[8][4];
#pragma unroll
    for (int j = 0; j < 8; j++)
#pragma unroll
        for (int q = 0; q < 4; q++) acc[j][q] = 0.f;

    for (int ks = 0; ks < 8; ks++) {
        const int i0 = (sp * 8 + ks) * 64;
        // async w1 slab (raw f32)
        for (int i = tid; i < 2048; i += 256) {
            int o = i >> 4, c4 = (i & 15) << 2;
            CPA16(smu32(As + o * 68 + c4), w1 + (size_t)o * HW + i0 + c4);
        }
        CPA_COMMIT();
        // sync featk slab (scale + cvt) — overlaps the cp.async above
        for (int i = tid; i < 1024; i += 256) {
            int r = i >> 4, c4 = (i & 15) << 2;
            float s = __ldg(g_scale_buf + b * HW + i0 + r);
            float4 v = *reinterpret_cast<const float4*>(
                feat + ((size_t)(b * HW + i0 + r)) * FD + c0 + c4);
            Bs[r * 68 + c4 + 0] = f2tf32(v.x * s);
            Bs[r * 68 + c4 + 1] = f2tf32(v.y * s);
            Bs[r * 68 + c4 + 2] = f2tf32(v.z * s);
            Bs[r * 68 + c4 + 3] = f2tf32(v.w * s);
        }
        CPA_WAIT0();
        __syncthreads();
#pragma unroll
        for (int kk = 0; kk < 8; kk++) {
            uint32_t a0 = fu(As[(wm * 16 + g) * 68 + kk * 8 + tg]);
            uint32_t a1 = fu(As[(wm * 16 + g + 8) * 68 + kk * 8 + tg]);
            uint32_t a2 = fu(As[(wm * 16 + g) * 68 + kk * 8 + tg + 4]);
            uint32_t a3 = fu(As[(wm * 16 + g + 8) * 68 + kk * 8 + tg + 4]);
#pragma unroll
            for (int j = 0; j < 8; j++) {
                uint32_t bb0 = fu(Bs[(kk * 8 + tg) * 68 + j * 8 + g]);
                uint32_t bb1 = fu(Bs[(kk * 8 + tg + 4) * 68 + j * 8 + g]);
                mma_tf32(acc[j], a0, a1, a2, a3, bb0, bb1);
            }
        }
        __syncthreads();   // protects next iter's As/Bs overwrite
    }

    // write partials (no bias/relu): g_part[sp][b][o][c]
    float* dst = g_part + ((size_t)(sp * NB + b) * HS) * FD;
    const int o0 = wm * 16 + g;
#pragma unroll
    for (int j = 0; j < 8; j++) {
        int c = c0 + j * 8 + 2 * tg;
        *reinterpret_cast<float2*>(dst + o0 * FD + c)       = make_float2(acc[j][0], acc[j][1]);
        *reinterpret_cast<float2*>(dst + (o0 + 8) * FD + c) = make_float2(acc[j][2], acc[j][3]);
    }
}

// ---------------------------------------------------------------------------
// Kernel 3: split-K reduce + bias + relu + conv2 + emb_pos.
// grid 32 (batch), 256 threads (channel).
// ---------------------------------------------------------------------------
__global__ __launch_bounds__(256)
void k_sred(const float* __restrict__ b1v, const float* __restrict__ w2,
            const float* __restrict__ b2, const float* __restrict__ embp,
            float* __restrict__ outs) {
    __shared__ float w2s[NT * HS];
    const int b = blockIdx.x;
    const int c = threadIdx.x;
    for (int i = c; i < NT * HS; i += 256) w2s[i] = w2[i];
    __syncthreads();

    float at[NT];
#pragma unroll
    for (int t = 0; t < NT; t++) at[t] = 0.f;

    const float* pb = g_part + (size_t)b * (HS * FD) + c;
#pragma unroll 4
    for (int o = 0; o < HS; o++) {
        float h = 0.f;
#pragma unroll
        for (int s = 0; s < NSPLIT; s++)
            h += pb[((size_t)s * NB * HS + o) * FD];
        h = fmaxf(h + __ldg(b1v + o), 0.f);
#pragma unroll
        for (int t = 0; t < NT; t++) at[t] += h * w2s[t * HS + o];
    }
#pragma unroll
    for (int t = 0; t < NT; t++)
        outs[b * (NT * FD) + t * FD + c] = at[t] + __ldg(b2 + t) + __ldg(embp + t * FD + c);
}

// ---------------------------------------------------------------------------
// launcher
// ---------------------------------------------------------------------------
extern "C" void kernel_launch(void* const* d_in, const int* in_sizes, int n_in,
                              void* d_out, int out_size) {
    (void)out_size;
    const float* feat  = (const float*)d_in[0];
    const float* proto = (const float*)d_in[1];
    // d_in[2] = cls_ids (all ones). num_classes may or may not be materialized.
    int s = (n_in >= 14) ? 0 : -1;
    if (in_sizes[4 + s] != HD * FD) {
        if (in_sizes[3] == HD * FD)      s = -1;
        else if (in_sizes[4] == HD * FD) s = 0;
    }
    const float* w_d1 = (const float*)d_in[4 + s];
    const float* b_d1 = (const float*)d_in[5 + s];
    const float* w_d2 = (const float*)d_in[6 + s];
    const float* b_d2 = (const float*)d_in[7 + s];
    const float* w_s1 = (const float*)d_in[8 + s];
    const float* b_s1 = (const float*)d_in[9 + s];
    const float* w_s2 = (const float*)d_in[10 + s];
    const float* b_s2 = (const float*)d_in[11 + s];
    const float* embp = (const float*)d_in[13 + s];   // emb_pos (one_hot == 1)
    float* out = (float*)d_out;

    cudaFuncSetAttribute(k_dense,  cudaFuncAttributeMaxDynamicSharedMemorySize, K2_SMEM_BYTES);
    cudaFuncSetAttribute(k_sparse, cudaFuncAttributeMaxDynamicSharedMemorySize, K3_SMEM_BYTES);

    // dense path + (1+sim) scratch
    k_dense<<<dim3(32, 64), 256, K2_SMEM_BYTES>>>(feat, proto, w_d1, b_d1, w_d2, b_d2, out);
    // sparse conv1 split-K (needs g_scale_buf: same stream -> ordered)
    k_sparse<<<dim3(4, 32, NSPLIT), 256, K3_SMEM_BYTES>>>(feat, w_s1);
    // reduce + conv2 + embeddings
    k_sred<<<32, 256>>>(b_s1, w_s2, b_s2, embp, out + DENSE_OUT_ELEMS);
}